// round 1
// baseline (speedup 1.0000x reference)
#include <cuda_runtime.h>
#include <cuda_bf16.h>

// ---------------- problem constants ----------------
#define A_N   76725
#define NCLS  80
#define NB    8
#define KPRE  256
#define MDPC  100
#define MAXD  100
#define SORTN 2048   // candidate sort width in k_select
#define FINALN 8192  // image-level sort width

// ---------------- scratch (device globals; no runtime alloc) ----------------
__device__ unsigned int g_keys[(size_t)NB * NCLS * A_N];   // [b][c][a] monotonic score keys (~187MB)
__device__ float4       g_boxes[(size_t)NB * A_N];          // decoded corner boxes
__device__ float        g_cls_scores[NB * NCLS * MDPC];     // per-class NMS'd scores (-1 invalid)
__device__ float4       g_cls_boxes[NB * NCLS * MDPC];

// =====================================================================
// Kernel 1: decode boxes + sigmoid scores -> transposed key array
// =====================================================================
__global__ void __launch_bounds__(256) k_decode(const float* __restrict__ pred,
                                                const float* __restrict__ anchors) {
    __shared__ float sp[128 * 85];               // 128 anchors x 84 (padded to 85)
    const int nT = (A_N + 127) >> 7;             // 600 tiles
    const int b  = blockIdx.x / nT;
    const int t  = blockIdx.x % nT;
    const int a0 = t << 7;
    const int na = min(128, A_N - a0);

    const float* src = pred + ((size_t)b * A_N + a0) * 84;
    const int tot = na * 84;
    for (int i = threadIdx.x; i < tot; i += 256) {
        int la = i / 84;
        sp[la * 85 + (i - la * 84)] = src[i];
    }
    __syncthreads();

    // box decode (threads 0..na-1)
    if (threadIdx.x < na) {
        const int la = threadIdx.x;
        const float4 an = ((const float4*)anchors)[a0 + la];
        float tx = sp[la * 85 + 0] * 0.1f;
        float ty = sp[la * 85 + 1] * 0.1f;
        float tw = sp[la * 85 + 2] * 0.2f;
        float th = sp[la * 85 + 3] * 0.2f;
        float cx = tx * an.z + an.x;
        float cy = ty * an.w + an.y;
        float w  = expf(tw) * an.z;
        float h  = expf(th) * an.w;
        g_boxes[(size_t)b * A_N + a0 + la] =
            make_float4(cx - w * 0.5f, cy - h * 0.5f, cx + w * 0.5f, cy + h * 0.5f);
    }

    // scores: 80 classes x 128 anchors = 40 iterations of 256 threads
    for (int it = 0; it < 40; ++it) {
        int idx = it * 256 + threadIdx.x;
        int c  = idx >> 7;
        int la = idx & 127;
        if (la < na) {
            float x = sp[la * 85 + 4 + c];
            float s = 1.0f / (1.0f + expf(-x));
            unsigned key = (s > 0.05f) ? (__float_as_uint(s) | 0x80000000u) : 0u;
            g_keys[(size_t)(b * NCLS + c) * A_N + a0 + la] = key;
        }
    }
}

// =====================================================================
// Kernel 2: per (b,c) exact top-256 (radix select) + greedy NMS + top-100
// =====================================================================
__device__ __forceinline__ unsigned block_suffix_total(unsigned* hist, unsigned* csum, int tid) {
    unsigned s = 0;
    const int base = tid * 32;
    for (int r = 0; r < 32; ++r) s += hist[base + r];
    csum[tid] = s;
    __syncthreads();
    for (int off = 1; off < 256; off <<= 1) {
        unsigned add = (tid + off < 256) ? csum[tid + off] : 0u;
        __syncthreads();
        csum[tid] += add;
        __syncthreads();
    }
    return csum[0];
}

__device__ __forceinline__ void block_crossing(unsigned* hist, unsigned* csum, int* ctrl,
                                               unsigned target, int tid) {
    unsigned run = (tid + 1 < 256) ? csum[tid + 1] : 0u;
    const int base = tid * 32;
    for (int i = base + 31; i >= base; --i) {
        unsigned h = hist[i];
        run += h;
        if (run >= target && run - h < target) { ctrl[0] = i; ctrl[1] = (int)(run - h); }
    }
    __syncthreads();
}

__global__ void __launch_bounds__(256) k_select() {
    extern __shared__ unsigned char sm[];
    unsigned*           hist = (unsigned*)sm;                         // 8192 u32 (32KB)
    unsigned long long* buf  = (unsigned long long*)(sm + 32768);     // 2048 u64 (16KB)
    unsigned*           csum = (unsigned*)(sm + 49152);               // 257 u32
    int*                ctrl = (int*)(sm + 50180);                    // 8 ints

    const int tid  = threadIdx.x;
    const int task = blockIdx.x;
    const int b    = task / NCLS;
    const unsigned* keys = g_keys + (size_t)task * A_N;

    // -------- pass 1: histogram of key bits [31:19] --------
    for (int i = tid; i < 8192; i += 256) hist[i] = 0;
    __syncthreads();
    for (int i = tid; i < A_N; i += 256) {
        unsigned v = keys[i];
        if (v) atomicAdd(&hist[v >> 19], 1u);
    }
    __syncthreads();

    unsigned tot = block_suffix_total(hist, csum, tid);
    unsigned target = tot < (unsigned)KPRE ? tot : (unsigned)KPRE;
    if (tot == 0u) {
        for (int p = tid; p < MDPC; p += 256) {
            g_cls_scores[task * MDPC + p] = -1.0f;
            g_cls_boxes[task * MDPC + p]  = make_float4(0.f, 0.f, 0.f, 0.f);
        }
        return;
    }
    block_crossing(hist, csum, ctrl, target, tid);
    const int      B1 = ctrl[0];
    const unsigned C1 = (unsigned)ctrl[1];
    __syncthreads();

    // -------- pass 2: refine within bin B1 on bits [18:6] --------
    for (int i = tid; i < 8192; i += 256) hist[i] = 0;
    __syncthreads();
    for (int i = tid; i < A_N; i += 256) {
        unsigned v = keys[i];
        if (v && (int)(v >> 19) == B1) atomicAdd(&hist[(v >> 6) & 0x1FFFu], 1u);
    }
    __syncthreads();
    (void)block_suffix_total(hist, csum, tid);
    block_crossing(hist, csum, ctrl, target - C1, tid);
    const int B2 = ctrl[0];
    __syncthreads();

    // -------- pass 3: collect candidates (strictly above + tie bin) --------
    if (tid == 0) ctrl[2] = 0;
    __syncthreads();
    for (int i = tid; i < A_N; i += 256) {
        unsigned v = keys[i];
        if (!v) continue;
        int h1 = (int)(v >> 19);
        bool take = h1 > B1;
        if (!take && h1 == B1) take = (int)((v >> 6) & 0x1FFFu) >= B2;
        if (take) {
            int p = atomicAdd(&ctrl[2], 1);
            if (p < SORTN)
                buf[p] = ((unsigned long long)v << 32) | (unsigned)(~(unsigned)i);
        }
    }
    __syncthreads();
    int cnt = ctrl[2]; if (cnt > SORTN) cnt = SORTN;
    for (int i = cnt + tid; i < SORTN; i += 256) buf[i] = 0ull;
    __syncthreads();

    // -------- bitonic sort descending (2048 x u64) --------
    for (int kk = 2; kk <= SORTN; kk <<= 1) {
        for (int j = kk >> 1; j > 0; j >>= 1) {
            for (int i = tid; i < SORTN; i += 256) {
                int ix = i ^ j;
                if (ix > i) {
                    unsigned long long x = buf[i], y = buf[ix];
                    bool sw = ((i & kk) == 0) ? (x < y) : (x > y);
                    if (sw) { buf[i] = y; buf[ix] = x; }
                }
            }
            __syncthreads();
        }
    }

    // -------- NMS on top-256 (reuse hist region for NMS state) --------
    float*    X1    = (float*)sm;
    float*    Y1    = (float*)(sm + 1024);
    float*    X2    = (float*)(sm + 2048);
    float*    Y2    = (float*)(sm + 3072);
    float*    AR    = (float*)(sm + 4096);
    float*    SC    = (float*)(sm + 5120);
    unsigned* MASKS = (unsigned*)(sm + 6144);    // [256][8]
    unsigned* KEEPW = (unsigned*)(sm + 14336);   // [8]
    unsigned* WPFX  = (unsigned*)(sm + 14400);   // [9]

    {
        unsigned long long e = buf[tid];
        unsigned key  = (unsigned)(e >> 32);
        unsigned aidx = ~(unsigned)(e & 0xFFFFFFFFull);
        float   s  = -1.0f;
        float4  bx = make_float4(0.f, 0.f, 0.f, 0.f);
        if (key) {
            s  = __uint_as_float(key & 0x7FFFFFFFu);
            bx = g_boxes[(size_t)b * A_N + aidx];
        }
        X1[tid] = bx.x; Y1[tid] = bx.y; X2[tid] = bx.z; Y2[tid] = bx.w;
        AR[tid] = (bx.z - bx.x) * (bx.w - bx.y);
        SC[tid] = s;
        unsigned bal = __ballot_sync(0xFFFFFFFFu, key != 0u);
        if ((tid & 31) == 0) KEEPW[tid >> 5] = bal;
    }
    __syncthreads();

    {   // suppression bitmask: row tid, bit j set iff j>tid and IoU>0.5
        float ax1 = X1[tid], ay1 = Y1[tid], ax2 = X2[tid], ay2 = Y2[tid], aa = AR[tid];
        for (int w = 0; w < 8; ++w) {
            unsigned m = 0;
            for (int l = 0; l < 32; ++l) {
                int j = w * 32 + l;
                if (j > tid) {
                    float ix1 = fmaxf(ax1, X1[j]);
                    float iy1 = fmaxf(ay1, Y1[j]);
                    float ix2 = fminf(ax2, X2[j]);
                    float iy2 = fminf(ay2, Y2[j]);
                    float iw = fmaxf(ix2 - ix1, 0.f);
                    float ih = fmaxf(iy2 - iy1, 0.f);
                    float inter = iw * ih;
                    float uni = aa + AR[j] - inter;
                    float iou = inter / fmaxf(uni, 1e-8f);
                    if (iou > 0.5f) m |= (1u << l);
                }
            }
            MASKS[tid * 8 + w] = m;
        }
    }
    __syncthreads();

    if (tid < 32) {   // sequential greedy pass (one warp, 8 active keep-words)
        unsigned kw = (tid < 8) ? KEEPW[tid] : 0u;
        for (int i = 0; i < 256; ++i) {
            unsigned word = __shfl_sync(0xFFFFFFFFu, kw, i >> 5);
            if ((word >> (i & 31)) & 1u) {
                if (tid < 8) kw &= ~MASKS[i * 8 + tid];
            }
        }
        if (tid < 8) KEEPW[tid] = kw;
    }
    __syncthreads();

    if (tid == 0) {
        unsigned run = 0;
        for (int w = 0; w < 8; ++w) { WPFX[w] = run; run += __popc(KEEPW[w]); }
        WPFX[8] = run;
    }
    __syncthreads();

    {   // per-class outputs: kept candidates (already in sorted order), pad with -1
        unsigned w = tid >> 5, bpos = tid & 31;
        unsigned kwv = KEEPW[w];
        bool kept = (kwv >> bpos) & 1u;
        unsigned p = WPFX[w] + __popc(kwv & ((1u << bpos) - 1u));
        if (kept && p < MDPC) {
            g_cls_scores[task * MDPC + p] = SC[tid];
            g_cls_boxes[task * MDPC + p]  = make_float4(X1[tid], Y1[tid], X2[tid], Y2[tid]);
        }
        int kc = (int)WPFX[8];
        for (int q = kc + tid; q < MDPC; q += 256) {
            g_cls_scores[task * MDPC + q] = -1.0f;
            g_cls_boxes[task * MDPC + q]  = make_float4(0.f, 0.f, 0.f, 0.f);
        }
    }
}

// =====================================================================
// Kernel 3: per image top-100 of 8000 (+ outputs)
// =====================================================================
__global__ void __launch_bounds__(512) k_final(float* __restrict__ out) {
    extern __shared__ unsigned char sm[];
    unsigned long long* sk = (unsigned long long*)sm;   // 8192 u64 (64KB)
    __shared__ int vc;
    const int tid = threadIdx.x;
    const int b   = blockIdx.x;

    for (int i = tid; i < FINALN; i += 512) {
        unsigned long long e = 0ull;
        if (i < NCLS * MDPC) {
            float s = g_cls_scores[b * NCLS * MDPC + i];
            unsigned bt = __float_as_uint(s);
            unsigned m = (bt & 0x80000000u) ? ~bt : (bt | 0x80000000u);
            e = ((unsigned long long)m << 32) | (unsigned)(~(unsigned)i);
        }
        sk[i] = e;
    }
    __syncthreads();

    for (int kk = 2; kk <= FINALN; kk <<= 1) {
        for (int j = kk >> 1; j > 0; j >>= 1) {
            for (int i = tid; i < FINALN; i += 512) {
                int ix = i ^ j;
                if (ix > i) {
                    unsigned long long x = sk[i], y = sk[ix];
                    bool sw = ((i & kk) == 0) ? (x < y) : (x > y);
                    if (sw) { sk[i] = y; sk[ix] = x; }
                }
            }
            __syncthreads();
        }
    }

    if (tid == 0) vc = 0;
    __syncthreads();

    if (tid < MAXD) {
        unsigned long long e = sk[tid];
        unsigned m    = (unsigned)(e >> 32);
        unsigned flat = ~(unsigned)(e & 0xFFFFFFFFull);
        unsigned bt = (m & 0x80000000u) ? (m & 0x7FFFFFFFu) : ~m;
        float s = __uint_as_float(bt);
        bool valid = (s > 0.0f);
        float4 bx = make_float4(0.f, 0.f, 0.f, 0.f);
        float cls = 0.0f, so = 0.0f;
        if (valid) {
            bx  = g_cls_boxes[b * NCLS * MDPC + flat];
            cls = (float)(flat / MDPC);
            so  = s;
            atomicAdd(&vc, 1);
        }
        out[b * 400 + tid * 4 + 0] = bx.x;
        out[b * 400 + tid * 4 + 1] = bx.y;
        out[b * 400 + tid * 4 + 2] = bx.z;
        out[b * 400 + tid * 4 + 3] = bx.w;
        out[NB * MAXD * 4 + b * MAXD + tid]             = so;   // scores @3200
        out[NB * MAXD * 4 + NB * MAXD + b * MAXD + tid] = cls;  // classes @4000
    }
    __syncthreads();
    if (tid == 0) out[NB * MAXD * 6 + b] = (float)vc;           // valid @4800
}

// =====================================================================
extern "C" void kernel_launch(void* const* d_in, const int* in_sizes, int n_in,
                              void* d_out, int out_size) {
    (void)in_sizes; (void)n_in; (void)out_size;
    const float* pred    = (const float*)d_in[1];  // [8,76725,84]
    const float* anchors = (const float*)d_in[2];  // [76725,4]
    float* out = (float*)d_out;

    const int nT = (A_N + 127) >> 7;               // 600
    k_decode<<<NB * nT, 256>>>(pred, anchors);

    cudaFuncSetAttribute(k_select, cudaFuncAttributeMaxDynamicSharedMemorySize, 50304);
    k_select<<<NB * NCLS, 256, 50304>>>();

    cudaFuncSetAttribute(k_final, cudaFuncAttributeMaxDynamicSharedMemorySize, 65536);
    k_final<<<NB, 512, 65536>>>(out);
}

// round 2
// speedup vs baseline: 1.0004x; 1.0004x over previous
#include <cuda_runtime.h>
#include <cuda_bf16.h>

// ---------------- problem constants ----------------
#define A_N   76725
#define NCLS  80
#define NB    8
#define KPRE  256
#define MDPC  100
#define MAXD  100
#define SORTN 2048   // candidate sort width in k_select
#define FINALN 8192  // image-level sort width

// ---------------- scratch (device globals; no runtime alloc) ----------------
__device__ unsigned int g_keys[(size_t)NB * NCLS * A_N];   // [b][c][a] monotonic score keys (~187MB)
__device__ float4       g_boxes[(size_t)NB * A_N];          // decoded corner boxes
__device__ float        g_cls_scores[NB * NCLS * MDPC];     // per-class NMS'd scores (-1 invalid)
__device__ float4       g_cls_boxes[NB * NCLS * MDPC];

// =====================================================================
// Kernel 1: decode boxes + sigmoid scores -> transposed key array
// =====================================================================
__global__ void __launch_bounds__(256) k_decode(const float* __restrict__ pred,
                                                const float* __restrict__ anchors) {
    __shared__ float sp[128 * 85];               // 128 anchors x 84 (padded to 85)
    const int nT = (A_N + 127) >> 7;             // 600 tiles
    const int b  = blockIdx.x / nT;
    const int t  = blockIdx.x % nT;
    const int a0 = t << 7;
    const int na = min(128, A_N - a0);

    const float* src = pred + ((size_t)b * A_N + a0) * 84;
    const int tot = na * 84;
    for (int i = threadIdx.x; i < tot; i += 256) {
        int la = i / 84;
        sp[la * 85 + (i - la * 84)] = src[i];
    }
    __syncthreads();

    // box decode (threads 0..na-1)
    if (threadIdx.x < na) {
        const int la = threadIdx.x;
        const float4 an = ((const float4*)anchors)[a0 + la];
        float tx = sp[la * 85 + 0] * 0.1f;
        float ty = sp[la * 85 + 1] * 0.1f;
        float tw = sp[la * 85 + 2] * 0.2f;
        float th = sp[la * 85 + 3] * 0.2f;
        float cx = tx * an.z + an.x;
        float cy = ty * an.w + an.y;
        float w  = expf(tw) * an.z;
        float h  = expf(th) * an.w;
        g_boxes[(size_t)b * A_N + a0 + la] =
            make_float4(cx - w * 0.5f, cy - h * 0.5f, cx + w * 0.5f, cy + h * 0.5f);
    }

    // scores: 80 classes x 128 anchors = 40 iterations of 256 threads
    for (int it = 0; it < 40; ++it) {
        int idx = it * 256 + threadIdx.x;
        int c  = idx >> 7;
        int la = idx & 127;
        if (la < na) {
            float x = sp[la * 85 + 4 + c];
            float s = 1.0f / (1.0f + expf(-x));
            unsigned key = (s > 0.05f) ? (__float_as_uint(s) | 0x80000000u) : 0u;
            g_keys[(size_t)(b * NCLS + c) * A_N + a0 + la] = key;
        }
    }
}

// =====================================================================
// Kernel 2: per (b,c) exact top-256 (radix select) + greedy NMS + top-100
// =====================================================================
__device__ __forceinline__ unsigned block_suffix_total(unsigned* hist, unsigned* csum, int tid) {
    unsigned s = 0;
    const int base = tid * 32;
    for (int r = 0; r < 32; ++r) s += hist[base + r];
    csum[tid] = s;
    __syncthreads();
    for (int off = 1; off < 256; off <<= 1) {
        unsigned add = (tid + off < 256) ? csum[tid + off] : 0u;
        __syncthreads();
        csum[tid] += add;
        __syncthreads();
    }
    return csum[0];
}

__device__ __forceinline__ void block_crossing(unsigned* hist, unsigned* csum, int* ctrl,
                                               unsigned target, int tid) {
    unsigned run = (tid + 1 < 256) ? csum[tid + 1] : 0u;
    const int base = tid * 32;
    for (int i = base + 31; i >= base; --i) {
        unsigned h = hist[i];
        run += h;
        if (run >= target && run - h < target) { ctrl[0] = i; ctrl[1] = (int)(run - h); }
    }
    __syncthreads();
}

__global__ void __launch_bounds__(256) k_select() {
    extern __shared__ unsigned char sm[];
    unsigned*           hist = (unsigned*)sm;                         // 8192 u32 (32KB)
    unsigned long long* buf  = (unsigned long long*)(sm + 32768);     // 2048 u64 (16KB)
    unsigned*           csum = (unsigned*)(sm + 49152);               // 257 u32
    int*                ctrl = (int*)(sm + 50180);                    // 8 ints

    const int tid  = threadIdx.x;
    const int task = blockIdx.x;
    const int b    = task / NCLS;
    const unsigned* keys = g_keys + (size_t)task * A_N;

    // -------- pass 1: histogram of key bits [31:19] --------
    for (int i = tid; i < 8192; i += 256) hist[i] = 0;
    __syncthreads();
    for (int i = tid; i < A_N; i += 256) {
        unsigned v = keys[i];
        if (v) atomicAdd(&hist[v >> 19], 1u);
    }
    __syncthreads();

    unsigned tot = block_suffix_total(hist, csum, tid);
    unsigned target = tot < (unsigned)KPRE ? tot : (unsigned)KPRE;
    if (tot == 0u) {
        for (int p = tid; p < MDPC; p += 256) {
            g_cls_scores[task * MDPC + p] = -1.0f;
            g_cls_boxes[task * MDPC + p]  = make_float4(0.f, 0.f, 0.f, 0.f);
        }
        return;
    }
    block_crossing(hist, csum, ctrl, target, tid);
    const int      B1 = ctrl[0];
    const unsigned C1 = (unsigned)ctrl[1];
    __syncthreads();

    // -------- pass 2: refine within bin B1 on bits [18:6] --------
    for (int i = tid; i < 8192; i += 256) hist[i] = 0;
    __syncthreads();
    for (int i = tid; i < A_N; i += 256) {
        unsigned v = keys[i];
        if (v && (int)(v >> 19) == B1) atomicAdd(&hist[(v >> 6) & 0x1FFFu], 1u);
    }
    __syncthreads();
    (void)block_suffix_total(hist, csum, tid);
    block_crossing(hist, csum, ctrl, target - C1, tid);
    const int B2 = ctrl[0];
    __syncthreads();

    // -------- pass 3: collect candidates (strictly above + tie bin) --------
    if (tid == 0) ctrl[2] = 0;
    __syncthreads();
    for (int i = tid; i < A_N; i += 256) {
        unsigned v = keys[i];
        if (!v) continue;
        int h1 = (int)(v >> 19);
        bool take = h1 > B1;
        if (!take && h1 == B1) take = (int)((v >> 6) & 0x1FFFu) >= B2;
        if (take) {
            int p = atomicAdd(&ctrl[2], 1);
            if (p < SORTN)
                buf[p] = ((unsigned long long)v << 32) | (unsigned)(~(unsigned)i);
        }
    }
    __syncthreads();
    int cnt = ctrl[2]; if (cnt > SORTN) cnt = SORTN;
    for (int i = cnt + tid; i < SORTN; i += 256) buf[i] = 0ull;
    __syncthreads();

    // -------- bitonic sort descending (2048 x u64) --------
    for (int kk = 2; kk <= SORTN; kk <<= 1) {
        for (int j = kk >> 1; j > 0; j >>= 1) {
            for (int i = tid; i < SORTN; i += 256) {
                int ix = i ^ j;
                if (ix > i) {
                    unsigned long long x = buf[i], y = buf[ix];
                    bool sw = ((i & kk) == 0) ? (x < y) : (x > y);
                    if (sw) { buf[i] = y; buf[ix] = x; }
                }
            }
            __syncthreads();
        }
    }

    // -------- NMS on top-256 (reuse hist region for NMS state) --------
    float*    X1    = (float*)sm;
    float*    Y1    = (float*)(sm + 1024);
    float*    X2    = (float*)(sm + 2048);
    float*    Y2    = (float*)(sm + 3072);
    float*    AR    = (float*)(sm + 4096);
    float*    SC    = (float*)(sm + 5120);
    unsigned* MASKS = (unsigned*)(sm + 6144);    // [256][8]
    unsigned* KEEPW = (unsigned*)(sm + 14336);   // [8]
    unsigned* WPFX  = (unsigned*)(sm + 14400);   // [9]

    {
        unsigned long long e = buf[tid];
        unsigned key  = (unsigned)(e >> 32);
        unsigned aidx = ~(unsigned)(e & 0xFFFFFFFFull);
        float   s  = -1.0f;
        float4  bx = make_float4(0.f, 0.f, 0.f, 0.f);
        if (key) {
            s  = __uint_as_float(key & 0x7FFFFFFFu);
            bx = g_boxes[(size_t)b * A_N + aidx];
        }
        X1[tid] = bx.x; Y1[tid] = bx.y; X2[tid] = bx.z; Y2[tid] = bx.w;
        AR[tid] = (bx.z - bx.x) * (bx.w - bx.y);
        SC[tid] = s;
        unsigned bal = __ballot_sync(0xFFFFFFFFu, key != 0u);
        if ((tid & 31) == 0) KEEPW[tid >> 5] = bal;
    }
    __syncthreads();

    {   // suppression bitmask: row tid, bit j set iff j>tid and IoU>0.5
        float ax1 = X1[tid], ay1 = Y1[tid], ax2 = X2[tid], ay2 = Y2[tid], aa = AR[tid];
        for (int w = 0; w < 8; ++w) {
            unsigned m = 0;
            for (int l = 0; l < 32; ++l) {
                int j = w * 32 + l;
                if (j > tid) {
                    float ix1 = fmaxf(ax1, X1[j]);
                    float iy1 = fmaxf(ay1, Y1[j]);
                    float ix2 = fminf(ax2, X2[j]);
                    float iy2 = fminf(ay2, Y2[j]);
                    float iw = fmaxf(ix2 - ix1, 0.f);
                    float ih = fmaxf(iy2 - iy1, 0.f);
                    float inter = iw * ih;
                    float uni = aa + AR[j] - inter;
                    float iou = inter / fmaxf(uni, 1e-8f);
                    if (iou > 0.5f) m |= (1u << l);
                }
            }
            MASKS[tid * 8 + w] = m;
        }
    }
    __syncthreads();

    if (tid < 32) {   // sequential greedy pass (one warp, 8 active keep-words)
        unsigned kw = (tid < 8) ? KEEPW[tid] : 0u;
        for (int i = 0; i < 256; ++i) {
            unsigned word = __shfl_sync(0xFFFFFFFFu, kw, i >> 5);
            if ((word >> (i & 31)) & 1u) {
                if (tid < 8) kw &= ~MASKS[i * 8 + tid];
            }
        }
        if (tid < 8) KEEPW[tid] = kw;
    }
    __syncthreads();

    if (tid == 0) {
        unsigned run = 0;
        for (int w = 0; w < 8; ++w) { WPFX[w] = run; run += __popc(KEEPW[w]); }
        WPFX[8] = run;
    }
    __syncthreads();

    {   // per-class outputs: kept candidates (already in sorted order), pad with -1
        unsigned w = tid >> 5, bpos = tid & 31;
        unsigned kwv = KEEPW[w];
        bool kept = (kwv >> bpos) & 1u;
        unsigned p = WPFX[w] + __popc(kwv & ((1u << bpos) - 1u));
        if (kept && p < MDPC) {
            g_cls_scores[task * MDPC + p] = SC[tid];
            g_cls_boxes[task * MDPC + p]  = make_float4(X1[tid], Y1[tid], X2[tid], Y2[tid]);
        }
        int kc = (int)WPFX[8];
        for (int q = kc + tid; q < MDPC; q += 256) {
            g_cls_scores[task * MDPC + q] = -1.0f;
            g_cls_boxes[task * MDPC + q]  = make_float4(0.f, 0.f, 0.f, 0.f);
        }
    }
}

// =====================================================================
// Kernel 3: per image top-100 of 8000 (+ outputs)
// =====================================================================
__global__ void __launch_bounds__(512) k_final(float* __restrict__ out) {
    extern __shared__ unsigned char sm[];
    unsigned long long* sk = (unsigned long long*)sm;   // 8192 u64 (64KB)
    __shared__ int vc;
    const int tid = threadIdx.x;
    const int b   = blockIdx.x;

    for (int i = tid; i < FINALN; i += 512) {
        unsigned long long e = 0ull;
        if (i < NCLS * MDPC) {
            float s = g_cls_scores[b * NCLS * MDPC + i];
            unsigned bt = __float_as_uint(s);
            unsigned m = (bt & 0x80000000u) ? ~bt : (bt | 0x80000000u);
            e = ((unsigned long long)m << 32) | (unsigned)(~(unsigned)i);
        }
        sk[i] = e;
    }
    __syncthreads();

    for (int kk = 2; kk <= FINALN; kk <<= 1) {
        for (int j = kk >> 1; j > 0; j >>= 1) {
            for (int i = tid; i < FINALN; i += 512) {
                int ix = i ^ j;
                if (ix > i) {
                    unsigned long long x = sk[i], y = sk[ix];
                    bool sw = ((i & kk) == 0) ? (x < y) : (x > y);
                    if (sw) { sk[i] = y; sk[ix] = x; }
                }
            }
            __syncthreads();
        }
    }

    if (tid == 0) vc = 0;
    __syncthreads();

    if (tid < MAXD) {
        unsigned long long e = sk[tid];
        unsigned m    = (unsigned)(e >> 32);
        unsigned flat = ~(unsigned)(e & 0xFFFFFFFFull);
        unsigned bt = (m & 0x80000000u) ? (m & 0x7FFFFFFFu) : ~m;
        float s = __uint_as_float(bt);
        bool valid = (s > 0.0f);
        float4 bx = make_float4(0.f, 0.f, 0.f, 0.f);
        float cls = 0.0f, so = 0.0f;
        if (valid) {
            bx  = g_cls_boxes[b * NCLS * MDPC + flat];
            cls = (float)(flat / MDPC);
            so  = s;
            atomicAdd(&vc, 1);
        }
        out[b * 400 + tid * 4 + 0] = bx.x;
        out[b * 400 + tid * 4 + 1] = bx.y;
        out[b * 400 + tid * 4 + 2] = bx.z;
        out[b * 400 + tid * 4 + 3] = bx.w;
        out[NB * MAXD * 4 + b * MAXD + tid]             = so;   // scores @3200
        out[NB * MAXD * 4 + NB * MAXD + b * MAXD + tid] = cls;  // classes @4000
    }
    __syncthreads();
    if (tid == 0) out[NB * MAXD * 6 + b] = (float)vc;           // valid @4800
}

// =====================================================================
extern "C" void kernel_launch(void* const* d_in, const int* in_sizes, int n_in,
                              void* d_out, int out_size) {
    (void)in_sizes; (void)n_in; (void)out_size;
    const float* pred    = (const float*)d_in[1];  // [8,76725,84]
    const float* anchors = (const float*)d_in[2];  // [76725,4]
    float* out = (float*)d_out;

    const int nT = (A_N + 127) >> 7;               // 600
    k_decode<<<NB * nT, 256>>>(pred, anchors);

    cudaFuncSetAttribute(k_select, cudaFuncAttributeMaxDynamicSharedMemorySize, 50304);
    k_select<<<NB * NCLS, 256, 50304>>>();

    cudaFuncSetAttribute(k_final, cudaFuncAttributeMaxDynamicSharedMemorySize, 65536);
    k_final<<<NB, 512, 65536>>>(out);
}

// round 3
// speedup vs baseline: 1.2492x; 1.2487x over previous
#include <cuda_runtime.h>
#include <math.h>

#define A_N    76725
#define A_PAD  76800            // 600*128, key-padded with 0
#define NCLS   80
#define NB     8
#define NTASK  (NB*NCLS)
#define KPRE   256
#define MDPC   100
#define MAXD   100
#define CAPB   2048
#define FINALN 8192
#define TGKEY  0xC000u          // fkey32(2.0f)>>16 : speculative high cutoff

__device__ unsigned short g_keys16[(size_t)NTASK * A_PAD];  // ~98MB
__device__ float  g_cls_scores[NTASK * MDPC];
__device__ float4 g_cls_boxes[NTASK * MDPC];

__device__ __forceinline__ unsigned fkey32(float x) {
    unsigned b = __float_as_uint(x);
    return (b & 0x80000000u) ? ~b : (b | 0x80000000u);
}

__device__ __forceinline__ unsigned suffix_total(const unsigned* hist, unsigned* csum, int tid) {
    unsigned s = 0;
    const int base = tid * 32;
#pragma unroll
    for (int r = 0; r < 32; ++r) s += hist[base + r];
    csum[tid] = s;
    __syncthreads();
    for (int off = 1; off < 256; off <<= 1) {
        unsigned add = (tid + off < 256) ? csum[tid + off] : 0u;
        __syncthreads();
        csum[tid] += add;
        __syncthreads();
    }
    return csum[0];
}

__device__ __forceinline__ void crossing(const unsigned* hist, const unsigned* csum, int* ctrl,
                                         unsigned target, int tid) {
    unsigned run = (tid + 1 < 256) ? csum[tid + 1] : 0u;
    const int base = tid * 32;
    for (int i = base + 31; i >= base; --i) {
        unsigned h = hist[i];
        run += h;
        if (run >= target && run - h < target) ctrl[0] = i;
    }
    __syncthreads();
}

// =====================================================================
// Kernel 1: transpose logits -> 16-bit monotonic keys (no sigmoid)
// =====================================================================
__global__ void __launch_bounds__(256) k_decode(const float* __restrict__ pred) {
    __shared__ float sp[128 * 85];
    const int nT = A_PAD / 128;                 // 600
    const int b  = blockIdx.x / nT;
    const int t  = blockIdx.x % nT;
    const int a0 = t << 7;
    const int na = min(128, A_N - a0);

    const float4* src4 = (const float4*)(pred + ((size_t)b * A_N + a0) * 84);
    const int tot4 = na * 21;
    for (int i = threadIdx.x; i < tot4; i += 256) {
        float4 v = src4[i];
        int la = i / 21;
        float* d = &sp[la * 85 + (i - la * 21) * 4];
        d[0] = v.x; d[1] = v.y; d[2] = v.z; d[3] = v.w;
    }
    __syncthreads();

    for (int it = 0; it < 20; ++it) {
        int q = it * 256 + threadIdx.x;          // 0..5119 = 80 classes * 64 pairs
        int c = q >> 6, p = q & 63;
        int la0 = p * 2;
        unsigned k0 = 0, k1 = 0;
        if (la0     < na) { float x = sp[la0 * 85 + 89 + c - 85]; x = sp[la0 * 85 + 4 + c]; if (x > -3.0f) k0 = fkey32(x) >> 16; }
        if (la0 + 1 < na) { float x = sp[(la0 + 1) * 85 + 4 + c]; if (x > -3.0f) k1 = fkey32(x) >> 16; }
        unsigned* row = (unsigned*)(g_keys16 + (size_t)(b * NCLS + c) * A_PAD + a0);
        row[p] = k0 | (k1 << 16);
    }
}

// =====================================================================
// Kernel 2: per (b,c) exact top-256 + greedy NMS + per-class top-100
// =====================================================================
__global__ void __launch_bounds__(256) k_select(const float* __restrict__ pred,
                                                const float* __restrict__ anchors) {
    extern __shared__ unsigned char sm[];
    unsigned*           hist = (unsigned*)sm;                      // 32KB
    unsigned long long* buf  = (unsigned long long*)(sm + 32768);  // 16KB
    unsigned*           csum = (unsigned*)(sm + 49152);            // 257 u32
    int*                ctrl = (int*)(sm + 50192);

    const int tid  = threadIdx.x;
    const int task = blockIdx.x;
    const int b    = task / NCLS;
    const int c    = task % NCLS;
    const uint4* k4 = (const uint4*)(g_keys16 + (size_t)task * A_PAD);

    for (int i = tid; i < 8192; i += 256) hist[i] = 0;
    if (tid < 8) ctrl[tid] = 0;
    __syncthreads();

    // ---- pass 1: counts (no atomics) + speculative high-range histogram ----
    unsigned c_all = 0, c_hi = 0;
    for (int u = tid; u < A_PAD / 8; u += 256) {
        uint4 v = k4[u];
        unsigned kk[8] = { v.x & 0xFFFFu, v.x >> 16, v.y & 0xFFFFu, v.y >> 16,
                           v.z & 0xFFFFu, v.z >> 16, v.w & 0xFFFFu, v.w >> 16 };
#pragma unroll
        for (int j = 0; j < 8; ++j) {
            unsigned k = kk[j];
            c_all += (k != 0u);
            if (k >= TGKEY) { ++c_hi; atomicAdd(&hist[(k - TGKEY) >> 1], 1u); }
        }
    }
    for (int o = 16; o; o >>= 1) {
        c_all += __shfl_down_sync(0xFFFFFFFFu, c_all, o);
        c_hi  += __shfl_down_sync(0xFFFFFFFFu, c_hi,  o);
    }
    if ((tid & 31) == 0) {
        atomicAdd((unsigned*)&ctrl[5], c_all);
        atomicAdd((unsigned*)&ctrl[6], c_hi);
    }
    __syncthreads();

    const unsigned total = (unsigned)ctrl[5];
    const unsigned hi    = (unsigned)ctrl[6];
    if (total == 0u) {
        for (int p = tid; p < MDPC; p += 256) {
            g_cls_scores[task * MDPC + p] = -1.0f;
            g_cls_boxes [task * MDPC + p] = make_float4(0.f, 0.f, 0.f, 0.f);
        }
        return;
    }
    const unsigned target = total < (unsigned)KPRE ? total : (unsigned)KPRE;

    unsigned collectMin;
    if (hi >= target) {
        (void)suffix_total(hist, csum, tid);
        crossing(hist, csum, ctrl, target, tid);
        unsigned cm = TGKEY + ((unsigned)ctrl[0] << 1);
        __syncthreads();
        collectMin = (cm > 1u) ? cm - 1u : 1u;
    } else {
        // exact fallback: full-range histogram (bins = key>>3)
        for (int i = tid; i < 8192; i += 256) hist[i] = 0;
        __syncthreads();
        for (int u = tid; u < A_PAD / 8; u += 256) {
            uint4 v = k4[u];
            unsigned kk[8] = { v.x & 0xFFFFu, v.x >> 16, v.y & 0xFFFFu, v.y >> 16,
                               v.z & 0xFFFFu, v.z >> 16, v.w & 0xFFFFu, v.w >> 16 };
#pragma unroll
            for (int j = 0; j < 8; ++j)
                if (kk[j]) atomicAdd(&hist[kk[j] >> 3], 1u);
        }
        __syncthreads();
        (void)suffix_total(hist, csum, tid);
        crossing(hist, csum, ctrl, target, tid);
        unsigned cm = (unsigned)ctrl[0] << 3;
        __syncthreads();
        collectMin = (cm > 1u) ? cm - 1u : 1u;
    }

    if (tid == 0) ctrl[2] = 0;
    __syncthreads();

    // ---- pass 2: collect candidates, exact sigmoid score ----
    for (int u = tid; u < A_PAD / 8; u += 256) {
        uint4 v = k4[u];
        unsigned kk[8] = { v.x & 0xFFFFu, v.x >> 16, v.y & 0xFFFFu, v.y >> 16,
                           v.z & 0xFFFFu, v.z >> 16, v.w & 0xFFFFu, v.w >> 16 };
#pragma unroll
        for (int j = 0; j < 8; ++j) {
            if (kk[j] >= collectMin) {
                int slot = atomicAdd(&ctrl[2], 1);
                if (slot < CAPB) {
                    int a = u * 8 + j;
                    float x = pred[((size_t)b * A_N + a) * 84 + 4 + c];
                    float s = 1.0f / (1.0f + expf(-x));
                    unsigned long long e = 0ull;
                    if (s > 0.05f)
                        e = ((unsigned long long)(__float_as_uint(s) | 0x80000000u) << 32)
                          | (unsigned)(~(unsigned)a);
                    buf[slot] = e;
                }
            }
        }
    }
    __syncthreads();
    int cnt = ctrl[2]; if (cnt > CAPB) cnt = CAPB;
    const int W = (cnt <= 512) ? 512 : ((cnt <= 1024) ? 1024 : 2048);
    for (int i = cnt + tid; i < W; i += 256) buf[i] = 0ull;
    __syncthreads();

    // ---- bitonic sort descending over W u64 ----
    for (int kk2 = 2; kk2 <= W; kk2 <<= 1) {
        for (int j = kk2 >> 1; j > 0; j >>= 1) {
            for (int i = tid; i < W; i += 256) {
                int ix = i ^ j;
                if (ix > i) {
                    unsigned long long x = buf[i], y = buf[ix];
                    bool sw = ((i & kk2) == 0) ? (x < y) : (x > y);
                    if (sw) { buf[i] = y; buf[ix] = x; }
                }
            }
            __syncthreads();
        }
    }

    // ---- NMS on top-256 (aliases hist region) ----
    float*    X1    = (float*)sm;
    float*    Y1    = (float*)(sm + 1024);
    float*    X2    = (float*)(sm + 2048);
    float*    Y2    = (float*)(sm + 3072);
    float*    AR    = (float*)(sm + 4096);
    float*    SC    = (float*)(sm + 5120);
    unsigned* MASKS = (unsigned*)(sm + 6144);
    unsigned* KEEPW = (unsigned*)(sm + 14336);
    unsigned* WPFX  = (unsigned*)(sm + 14400);

    {
        unsigned long long e = buf[tid];
        unsigned key  = (unsigned)(e >> 32);
        unsigned aidx = ~(unsigned)(e & 0xFFFFFFFFull);
        float  s  = -1.0f;
        float4 bx = make_float4(0.f, 0.f, 0.f, 0.f);
        if (key) {
            const float4 bp = *(const float4*)(pred + ((size_t)b * A_N + aidx) * 84);
            const float4 an = ((const float4*)anchors)[aidx];
            float cx = bp.x * 0.1f * an.z + an.x;
            float cy = bp.y * 0.1f * an.w + an.y;
            float w  = expf(bp.z * 0.2f) * an.z;
            float h  = expf(bp.w * 0.2f) * an.w;
            bx = make_float4(cx - w * 0.5f, cy - h * 0.5f, cx + w * 0.5f, cy + h * 0.5f);
            s  = __uint_as_float(key & 0x7FFFFFFFu);
        }
        X1[tid] = bx.x; Y1[tid] = bx.y; X2[tid] = bx.z; Y2[tid] = bx.w;
        AR[tid] = (bx.z - bx.x) * (bx.w - bx.y);
        SC[tid] = s;
        unsigned bal = __ballot_sync(0xFFFFFFFFu, key != 0u);
        if ((tid & 31) == 0) KEEPW[tid >> 5] = bal;
    }
    __syncthreads();

    {
        float ax1 = X1[tid], ay1 = Y1[tid], ax2 = X2[tid], ay2 = Y2[tid], aa = AR[tid];
        for (int w = 0; w < 8; ++w) {
            unsigned m = 0;
            for (int l = 0; l < 32; ++l) {
                int j = w * 32 + l;
                if (j > tid) {
                    float iw = fmaxf(fminf(ax2, X2[j]) - fmaxf(ax1, X1[j]), 0.f);
                    float ih = fmaxf(fminf(ay2, Y2[j]) - fmaxf(ay1, Y1[j]), 0.f);
                    float inter = iw * ih;
                    float iou = inter / fmaxf(aa + AR[j] - inter, 1e-8f);
                    if (iou > 0.5f) m |= (1u << l);
                }
            }
            MASKS[tid * 8 + w] = m;
        }
    }
    __syncthreads();

    if (tid < 32) {
        unsigned kw = (tid < 8) ? KEEPW[tid] : 0u;
        for (int i = 0; i < 256; ++i) {
            unsigned word = __shfl_sync(0xFFFFFFFFu, kw, i >> 5);
            if ((word >> (i & 31)) & 1u) {
                if (tid < 8) kw &= ~MASKS[i * 8 + tid];
            }
        }
        if (tid < 8) KEEPW[tid] = kw;
    }
    __syncthreads();

    if (tid == 0) {
        unsigned run = 0;
        for (int w = 0; w < 8; ++w) { WPFX[w] = run; run += __popc(KEEPW[w]); }
        WPFX[8] = run;
    }
    __syncthreads();

    {
        unsigned w = tid >> 5, bpos = tid & 31;
        unsigned kwv = KEEPW[w];
        bool kept = (kwv >> bpos) & 1u;
        unsigned p = WPFX[w] + __popc(kwv & ((1u << bpos) - 1u));
        if (kept && p < MDPC) {
            g_cls_scores[task * MDPC + p] = SC[tid];
            g_cls_boxes [task * MDPC + p] = make_float4(X1[tid], Y1[tid], X2[tid], Y2[tid]);
        }
        int kc = (int)WPFX[8];
        for (int q = kc + tid; q < MDPC; q += 256) {
            g_cls_scores[task * MDPC + q] = -1.0f;
            g_cls_boxes [task * MDPC + q] = make_float4(0.f, 0.f, 0.f, 0.f);
        }
    }
}

// =====================================================================
// Kernel 3: per image top-100 of 8000 (+ outputs)
// =====================================================================
__global__ void __launch_bounds__(512) k_final(float* __restrict__ out) {
    extern __shared__ unsigned char sm[];
    unsigned long long* sk = (unsigned long long*)sm;
    __shared__ int vc;
    const int tid = threadIdx.x;
    const int b   = blockIdx.x;

    for (int i = tid; i < FINALN; i += 512) {
        unsigned long long e = 0ull;
        if (i < NCLS * MDPC) {
            float s = g_cls_scores[b * NCLS * MDPC + i];
            e = ((unsigned long long)fkey32(s) << 32) | (unsigned)(~(unsigned)i);
        }
        sk[i] = e;
    }
    __syncthreads();

    for (int kk = 2; kk <= FINALN; kk <<= 1) {
        for (int j = kk >> 1; j > 0; j >>= 1) {
            for (int i = tid; i < FINALN; i += 512) {
                int ix = i ^ j;
                if (ix > i) {
                    unsigned long long x = sk[i], y = sk[ix];
                    bool sw = ((i & kk) == 0) ? (x < y) : (x > y);
                    if (sw) { sk[i] = y; sk[ix] = x; }
                }
            }
            __syncthreads();
        }
    }

    if (tid == 0) vc = 0;
    __syncthreads();

    if (tid < MAXD) {
        unsigned long long e = sk[tid];
        unsigned m    = (unsigned)(e >> 32);
        unsigned flat = ~(unsigned)(e & 0xFFFFFFFFull);
        unsigned bt = (m & 0x80000000u) ? (m & 0x7FFFFFFFu) : ~m;
        float s = __uint_as_float(bt);
        bool valid = (s > 0.0f);
        float4 bx = make_float4(0.f, 0.f, 0.f, 0.f);
        float cls = 0.0f, so = 0.0f;
        if (valid) {
            bx  = g_cls_boxes[b * NCLS * MDPC + flat];
            cls = (float)(flat / MDPC);
            so  = s;
            atomicAdd(&vc, 1);
        }
        out[b * 400 + tid * 4 + 0] = bx.x;
        out[b * 400 + tid * 4 + 1] = bx.y;
        out[b * 400 + tid * 4 + 2] = bx.z;
        out[b * 400 + tid * 4 + 3] = bx.w;
        out[NB * MAXD * 4 + b * MAXD + tid]             = so;
        out[NB * MAXD * 4 + NB * MAXD + b * MAXD + tid] = cls;
    }
    __syncthreads();
    if (tid == 0) out[NB * MAXD * 6 + b] = (float)vc;
}

// =====================================================================
extern "C" void kernel_launch(void* const* d_in, const int* in_sizes, int n_in,
                              void* d_out, int out_size) {
    (void)in_sizes; (void)n_in; (void)out_size;
    const float* pred    = (const float*)d_in[1];
    const float* anchors = (const float*)d_in[2];
    float* out = (float*)d_out;

    k_decode<<<NB * (A_PAD / 128), 256>>>(pred);

    cudaFuncSetAttribute(k_select, cudaFuncAttributeMaxDynamicSharedMemorySize, 50304);
    k_select<<<NTASK, 256, 50304>>>(pred, anchors);

    cudaFuncSetAttribute(k_final, cudaFuncAttributeMaxDynamicSharedMemorySize, 65536);
    k_final<<<NB, 512, 65536>>>(out);
}